// round 4
// baseline (speedup 1.0000x reference)
#include <cuda_runtime.h>
#include <cuda_bf16.h>
#include <math.h>
#include <stdint.h>

#define B_N    8192
#define K_N    512
#define D_N    2048
#define Q_N    8
#define LOG2PI 1.8378770664093453f
#define EPSC   1e-5f

// ---------------- scratch (static __device__, no allocation) ----------------
__device__ __nv_bfloat16 g_XB[(size_t)B_N * D_N];   // X in bf16, 33.5 MB
__device__ __nv_bfloat16 g_WB[(size_t)4608 * D_N];  // [512 pm rows | 4096 PinvW rows] x D, bf16
__device__ float  g_T [(size_t)B_N * K_N];          // t1[b][k], 16 MB
__device__ float  g_S2[(size_t)B_N * K_N];          // off + 0.5 v^T Minv v, 16 MB
__device__ float  g_psi_inv[D_N];
__device__ float  g_logdetPsi;
__device__ float  g_r[B_N];
__device__ float  g_alpha[K_N * 8];
__device__ float  g_Sacc[K_N * 45];                 // 36 S + 8 wm + 1 mumu partials
__device__ float  g_wpm[K_N * 8];
__device__ float  g_Minv[K_N * 64];                 // 0.5 * M^-1 (0.5 folded in!)
__device__ float  g_logdetM[K_N];
__device__ float  g_mumu[K_N];
__device__ float  g_off[K_N];
__device__ double g_acc;

__device__ __forceinline__ float softplusf(float x) {
    return x > 20.0f ? x : log1pf(expf(x));
}
__device__ __forceinline__ uint32_t smem_u32(const void* p) {
    uint32_t a;
    asm("{ .reg .u64 t; cvta.to.shared.u64 t, %1; cvt.u32.u64 %0, t; }" : "=r"(a) : "l"(p));
    return a;
}
__device__ __forceinline__ void cp_async16(uint32_t saddr, const void* gaddr) {
    asm volatile("cp.async.cg.shared.global [%0], [%1], 16;" :: "r"(saddr), "l"(gaddr));
}

// ---------------- psi precompute ----------------
__global__ void k_psi(const float* __restrict__ psi_rho) {
    __shared__ float ssum;
    int tid = threadIdx.x;
    if (tid == 0) ssum = 0.0f;
    __syncthreads();
    float l = 0.0f;
    for (int d = tid; d < D_N; d += 256) {
        float p = softplusf(psi_rho[d]) + EPSC;
        g_psi_inv[d] = 1.0f / p;
        l += logf(p);
    }
    atomicAdd(&ssum, l);
    __syncthreads();
    if (tid == 0) g_logdetPsi = ssum;
}

// ---------------- X -> bf16 ----------------
__global__ void k_cvt(const float* __restrict__ x) {
    size_t i = ((size_t)blockIdx.x * 256 + threadIdx.x) * 8;
    float4 a = *(const float4*)(x + i);
    float4 b = *(const float4*)(x + i + 4);
    __nv_bfloat162 p0 = __float22bfloat162_rn(make_float2(a.x, a.y));
    __nv_bfloat162 p1 = __float22bfloat162_rn(make_float2(a.z, a.w));
    __nv_bfloat162 p2 = __float22bfloat162_rn(make_float2(b.x, b.y));
    __nv_bfloat162 p3 = __float22bfloat162_rn(make_float2(b.z, b.w));
    uint4 o;
    o.x = *(uint32_t*)&p0; o.y = *(uint32_t*)&p1;
    o.z = *(uint32_t*)&p2; o.w = *(uint32_t*)&p3;
    *(uint4*)(g_XB + i) = o;
}

// ---------------- pA: column norms -> alpha; zero Sacc ----------------
__global__ void pA(const float* __restrict__ dir_raw,
                   const float* __restrict__ scale_rho) {
    int k = blockIdx.x, tid = threadIdx.x;
    __shared__ float s_nsq[8];
    if (tid < 8)  s_nsq[tid] = 0.0f;
    if (tid < 45) g_Sacc[k * 45 + tid] = 0.0f;
    __syncthreads();
    const float* dirk = dir_raw + (size_t)k * D_N * Q_N;
    float ns[8];
#pragma unroll
    for (int j = 0; j < 8; j++) ns[j] = 0.0f;
    for (int d = tid; d < D_N; d += 256) {
        float4 a  = *(const float4*)(dirk + (size_t)d * 8);
        float4 b4 = *(const float4*)(dirk + (size_t)d * 8 + 4);
        ns[0] += a.x * a.x;  ns[1] += a.y * a.y;
        ns[2] += a.z * a.z;  ns[3] += a.w * a.w;
        ns[4] += b4.x * b4.x; ns[5] += b4.y * b4.y;
        ns[6] += b4.z * b4.z; ns[7] += b4.w * b4.w;
    }
#pragma unroll
    for (int j = 0; j < 8; j++) atomicAdd(&s_nsq[j], ns[j]);
    __syncthreads();
    if (tid < 8) {
        float sp = softplusf(scale_rho[k * 8 + tid]);
        g_alpha[k * 8 + tid] = sp / fmaxf(sqrtf(s_nsq[tid]), EPSC);
    }
}

// ---------------- pB: S/wm/mumu partials + Wcat writes (4-way D split) ------
__global__ void pB(const float* __restrict__ dir_raw,
                   const float* __restrict__ mu) {
    int k = blockIdx.y, chunk = blockIdx.x, tid = threadIdx.x;
    __shared__ float s_acc[45];
    if (tid < 45) s_acc[tid] = 0.0f;
    __syncthreads();

    const float* dirk = dir_raw + (size_t)k * D_N * Q_N;
    const float* muk  = mu + (size_t)k * D_N;
    float al[8];
#pragma unroll
    for (int j = 0; j < 8; j++) al[j] = g_alpha[k * 8 + j];

    float S[36], wm[8], mm = 0.0f;
#pragma unroll
    for (int i = 0; i < 36; i++) S[i] = 0.0f;
#pragma unroll
    for (int i = 0; i < 8; i++) wm[i] = 0.0f;

    int d0 = chunk * 512;
#pragma unroll
    for (int it = 0; it < 2; it++) {
        int d = d0 + tid + it * 256;
        float dv[8];
        float4 a  = *(const float4*)(dirk + (size_t)d * 8);
        float4 b4 = *(const float4*)(dirk + (size_t)d * 8 + 4);
        dv[0] = a.x; dv[1] = a.y; dv[2] = a.z; dv[3] = a.w;
        dv[4] = b4.x; dv[5] = b4.y; dv[6] = b4.z; dv[7] = b4.w;
        float pi = g_psi_inv[d];
        float m  = muk[d];
        float pim = pi * m;
        mm += m * pim;
        int idx = 0;
#pragma unroll
        for (int i = 0; i < 8; i++) {
            float pdi = pi * dv[i];
            wm[i] += m * pdi;
#pragma unroll
            for (int j = 0; j <= i; j++) S[idx++] += pdi * dv[j];
        }
        g_WB[(size_t)k * D_N + d] = __float2bfloat16(pim);
#pragma unroll
        for (int j = 0; j < 8; j++)
            g_WB[(size_t)(K_N + k * 8 + j) * D_N + d] = __float2bfloat16(pi * al[j] * dv[j]);
    }
#pragma unroll
    for (int i = 0; i < 36; i++) atomicAdd(&s_acc[i], S[i]);
#pragma unroll
    for (int j = 0; j < 8; j++) atomicAdd(&s_acc[36 + j], wm[j]);
    atomicAdd(&s_acc[44], mm);
    __syncthreads();
    if (tid < 45) atomicAdd(&g_Sacc[k * 45 + tid], s_acc[tid]);
}

// ---------------- pC: per-k Cholesky / inverse (one thread per k) -----------
__global__ void pC() {
    int k = blockIdx.x * 128 + threadIdx.x;
    if (k >= K_N) return;
    float al[8], acc45[45];
#pragma unroll
    for (int j = 0; j < 8; j++) al[j] = g_alpha[k * 8 + j];
    for (int i = 0; i < 45; i++) acc45[i] = g_Sacc[k * 45 + i];

    float Mm[8][8];
    int idx = 0;
    for (int i = 0; i < 8; i++)
        for (int j = 0; j <= i; j++)
            Mm[i][j] = al[i] * al[j] * acc45[idx++] + (i == j ? 1.0f : 0.0f);
    for (int i = 0; i < 8; i++) {
        for (int j = 0; j <= i; j++) {
            float s = Mm[i][j];
            for (int p = 0; p < j; p++) s -= Mm[i][p] * Mm[j][p];
            if (i == j) Mm[i][i] = sqrtf(s);
            else        Mm[i][j] = s / Mm[j][j];
        }
    }
    float ld = 0.0f;
    for (int i = 0; i < 8; i++) ld += logf(Mm[i][i]);
    g_logdetM[k] = 2.0f * ld;
    g_mumu[k]    = acc45[44];
    for (int j = 0; j < 8; j++) g_wpm[k * 8 + j] = al[j] * acc45[36 + j];

    float Li[8][8];
    for (int i = 0; i < 8; i++)
        for (int j = 0; j < 8; j++) Li[i][j] = 0.0f;
    for (int c = 0; c < 8; c++) {
        for (int i = c; i < 8; i++) {
            float s = (i == c) ? 1.0f : 0.0f;
            for (int p = c; p < i; p++) s -= Mm[i][p] * Li[p][c];
            Li[i][c] = s / Mm[i][i];
        }
    }
    for (int i = 0; i < 8; i++)
        for (int j = 0; j < 8; j++) {
            float s = 0.0f;
            for (int m2 = 0; m2 < 8; m2++) s += Li[m2][i] * Li[m2][j];
            g_Minv[(size_t)k * 64 + i * 8 + j] = 0.5f * s;   // fold the 0.5
        }
}

// ---------------- per-k offset ----------------
__global__ void k_off(const float* __restrict__ pi_logits) {
    __shared__ float buf[512];
    int t = threadIdx.x;
    float v = pi_logits[t];
    buf[t] = v;
    __syncthreads();
    for (int s = 256; s > 0; s >>= 1) {
        if (t < s) buf[t] = fmaxf(buf[t], buf[t + s]);
        __syncthreads();
    }
    float mx = buf[0];
    __syncthreads();
    buf[t] = expf(v - mx);
    __syncthreads();
    for (int s = 256; s > 0; s >>= 1) {
        if (t < s) buf[t] += buf[t + s];
        __syncthreads();
    }
    float lse = logf(buf[0]) + mx;
    g_off[t] = -0.5f * ((float)D_N * LOG2PI + g_logdetPsi + g_logdetM[t] + g_mumu[t])
               + v - lse;
}

// ---------------- r[b] = x^T Psi^-1 x ----------------
__global__ void k_xpx(const float* __restrict__ x) {
    int warp = threadIdx.x >> 5, lane = threadIdx.x & 31;
    int b = blockIdx.x * 8 + warp;
    const float* xb = x + (size_t)b * D_N;
    float s = 0.0f;
    for (int d = lane * 4; d < D_N; d += 128) {
        float4 xv = *(const float4*)(xb + d);
        float4 pv = *(const float4*)(g_psi_inv + d);
        s += xv.x * xv.x * pv.x + xv.y * xv.y * pv.y
           + xv.z * xv.z * pv.z + xv.w * xv.w * pv.w;
    }
    for (int o = 16; o; o >>= 1) s += __shfl_xor_sync(0xffffffffu, s, o);
    if (lane == 0) g_r[b] = s;
}

// ---------------- bf16 MMA GEMM + fused quad epilogue -----------------------
// CTA 256x128, warp tile 64x64, BK=32, 3-stage cp.async.
#define BK       32
#define KBLOCKS  (D_N / BK)          // 64
#define STAGES   3
#define TILE_A   (256 * 64)          // 16 KB
#define TILE_B   (128 * 64)          // 8 KB
#define TILE_AB  (TILE_A + TILE_B)   // 24 KB
#define SMEM_SZ  (STAGES * TILE_AB)  // 72 KB

__global__ void __launch_bounds__(256, 1) k_mma_gemm() {
    extern __shared__ char smem[];
    const int tid  = threadIdx.x;
    const int wid  = tid >> 5;
    const int lane = tid & 31;
    const int warp_m = wid & 3;    // 4 x 64 rows
    const int warp_n = wid >> 2;   // 2 x 64 cols
    const int bx = blockIdx.x;     // 0..35 (cols: bx<4 -> t1, else quad)
    const int by = blockIdx.y;     // 0..31 (256-row tiles)

    const uint32_t sbase = smem_u32(smem);
    const __nv_bfloat16* Ag = g_XB + (size_t)(by * 256) * D_N;
    const __nv_bfloat16* Bg = g_WB + (size_t)(bx * 128) * D_N;

    auto load_stage = [&](int s, int kb) {
        uint32_t aB = sbase + s * TILE_AB;
        uint32_t bB = aB + TILE_A;
#pragma unroll
        for (int i = 0; i < 4; i++) {
            int id = tid + i * 256;
            int row = id >> 2, ch = id & 3;
            int sw = ch ^ ((row >> 1) & 3);
            cp_async16(aB + row * 64 + sw * 16, Ag + (size_t)row * D_N + kb * BK + ch * 8);
        }
#pragma unroll
        for (int i = 0; i < 2; i++) {
            int id = tid + i * 256;
            int row = id >> 2, ch = id & 3;
            int sw = ch ^ ((row >> 1) & 3);
            cp_async16(bB + row * 64 + sw * 16, Bg + (size_t)row * D_N + kb * BK + ch * 8);
        }
        asm volatile("cp.async.commit_group;");
    };

    float acc[4][8][4];
#pragma unroll
    for (int mi = 0; mi < 4; mi++)
#pragma unroll
        for (int ni = 0; ni < 8; ni++)
#pragma unroll
            for (int j = 0; j < 4; j++) acc[mi][ni][j] = 0.0f;

    load_stage(0, 0);
    load_stage(1, 1);

    for (int kb = 0; kb < KBLOCKS; kb++) {
        if (kb + 2 < KBLOCKS) load_stage((kb + 2) % STAGES, kb + 2);
        if (kb < KBLOCKS - 2)      asm volatile("cp.async.wait_group 2;");
        else if (kb == KBLOCKS - 2) asm volatile("cp.async.wait_group 1;");
        else                        asm volatile("cp.async.wait_group 0;");
        __syncthreads();
        uint32_t aB = sbase + (kb % STAGES) * TILE_AB;
        uint32_t bB = aB + TILE_A;
#pragma unroll
        for (int ks = 0; ks < 2; ks++) {
            uint32_t a[4][4], b[8][2];
#pragma unroll
            for (int mi = 0; mi < 4; mi++) {
                int r  = warp_m * 64 + mi * 16 + (lane & 15);
                int ch = ks * 2 + (lane >> 4);
                uint32_t ad = aB + r * 64 + ((ch ^ ((r >> 1) & 3)) << 4);
                asm volatile("ldmatrix.sync.aligned.m8n8.x4.shared.b16 {%0,%1,%2,%3}, [%4];"
                             : "=r"(a[mi][0]), "=r"(a[mi][1]), "=r"(a[mi][2]), "=r"(a[mi][3])
                             : "r"(ad));
            }
#pragma unroll
            for (int p = 0; p < 4; p++) {
                int g  = lane >> 3, rl = lane & 7;
                int r  = warp_n * 64 + p * 16 + (g >> 1) * 8 + rl;
                int ch = ks * 2 + (g & 1);
                uint32_t bd = bB + r * 64 + ((ch ^ ((r >> 1) & 3)) << 4);
                asm volatile("ldmatrix.sync.aligned.m8n8.x4.shared.b16 {%0,%1,%2,%3}, [%4];"
                             : "=r"(b[2 * p][0]), "=r"(b[2 * p][1]),
                               "=r"(b[2 * p + 1][0]), "=r"(b[2 * p + 1][1])
                             : "r"(bd));
            }
#pragma unroll
            for (int mi = 0; mi < 4; mi++)
#pragma unroll
                for (int ni = 0; ni < 8; ni++) {
                    asm volatile(
                        "mma.sync.aligned.m16n8k16.row.col.f32.bf16.bf16.f32 "
                        "{%0,%1,%2,%3}, {%4,%5,%6,%7}, {%8,%9}, {%0,%1,%2,%3};"
                        : "+f"(acc[mi][ni][0]), "+f"(acc[mi][ni][1]),
                          "+f"(acc[mi][ni][2]), "+f"(acc[mi][ni][3])
                        : "r"(a[mi][0]), "r"(a[mi][1]), "r"(a[mi][2]), "r"(a[mi][3]),
                          "r"(b[ni][0]), "r"(b[ni][1]));
                }
        }
        __syncthreads();
    }

    const int gq = lane >> 2;   // 0..7
    const int tg = lane & 3;    // 0..3

    if (bx < 4) {
        // t1 region: plain write
#pragma unroll
        for (int mi = 0; mi < 4; mi++) {
            int r0 = by * 256 + warp_m * 64 + mi * 16 + gq;
            int r1 = r0 + 8;
#pragma unroll
            for (int ni = 0; ni < 8; ni++) {
                int col = bx * 128 + warp_n * 64 + ni * 8 + tg * 2;
                *(float2*)&g_T[(size_t)r0 * K_N + col] = make_float2(acc[mi][ni][0], acc[mi][ni][1]);
                *(float2*)&g_T[(size_t)r1 * K_N + col] = make_float2(acc[mi][ni][2], acc[mi][ni][3]);
            }
        }
        return;
    }

    // quad region: fused v^T (0.5 Minv) v epilogue
    float* sM = (float*)smem;            // 16 k x 64
    float* sW = sM + 16 * 64;            // 16 k x 8
    float* sO = sW + 16 * 8;             // 16
    int k0 = (bx - 4) * 16;
    for (int t = tid; t < 1024; t += 256)
        sM[t] = g_Minv[(size_t)(k0 + (t >> 6)) * 64 + (t & 63)];
    if (tid < 128) sW[tid] = g_wpm[k0 * 8 + tid];
    if (tid < 16)  sO[tid] = g_off[k0 + tid];
    __syncthreads();

    const unsigned FULL = 0xffffffffu;
    const bool oddg = (tg & 1);
    const bool hig  = (tg & 2);
#pragma unroll
    for (int ni = 0; ni < 8; ni++) {
        int k_loc = warp_n * 8 + ni;
        float m0[8], m1[8];
#pragma unroll
        for (int j = 0; j < 8; j++) {
            m0[j] = sM[k_loc * 64 + (2 * tg) * 8 + j];
            m1[j] = sM[k_loc * 64 + (2 * tg + 1) * 8 + j];
        }
        float w0 = sW[k_loc * 8 + 2 * tg];
        float w1 = sW[k_loc * 8 + 2 * tg + 1];
        float offk = sO[k_loc];
        int kg = k0 + k_loc;
#pragma unroll
        for (int mi = 0; mi < 4; mi++) {
            int r0 = by * 256 + warp_m * 64 + mi * 16 + gq;
            float q[2];
#pragma unroll
            for (int half = 0; half < 2; half++) {
                float va = acc[mi][ni][half * 2 + 0] - w0;   // j = 2tg
                float vb = acc[mi][ni][half * 2 + 1] - w1;   // j = 2tg+1
                float pa = __shfl_xor_sync(FULL, va, 1);
                float pb = __shfl_xor_sync(FULL, vb, 1);
                float u0 = oddg ? pa : va, u1 = oddg ? pb : vb;
                float u2 = oddg ? va : pa, u3 = oddg ? vb : pb;   // half-block 4h..4h+3
                float x0 = __shfl_xor_sync(FULL, u0, 2);
                float x1 = __shfl_xor_sync(FULL, u1, 2);
                float x2 = __shfl_xor_sync(FULL, u2, 2);
                float x3 = __shfl_xor_sync(FULL, u3, 2);
                float v0 = hig ? x0 : u0, v1 = hig ? x1 : u1;
                float v2 = hig ? x2 : u2, v3 = hig ? x3 : u3;
                float v4 = hig ? u0 : x0, v5 = hig ? u1 : x1;
                float v6 = hig ? u2 : x2, v7 = hig ? u3 : x3;
                float s0 = m0[0]*v0 + m0[1]*v1 + m0[2]*v2 + m0[3]*v3
                         + m0[4]*v4 + m0[5]*v5 + m0[6]*v6 + m0[7]*v7;
                float s1 = m1[0]*v0 + m1[1]*v1 + m1[2]*v2 + m1[3]*v3
                         + m1[4]*v4 + m1[5]*v5 + m1[6]*v6 + m1[7]*v7;
                float qp = va * s0 + vb * s1;
                qp += __shfl_xor_sync(FULL, qp, 1);
                qp += __shfl_xor_sync(FULL, qp, 2);
                q[half] = qp;
            }
            if (tg == 0) g_S2[(size_t)r0 * K_N + kg]        = offk + q[0];
            if (tg == 1) g_S2[(size_t)(r0 + 8) * K_N + kg]  = offk + q[1];
        }
    }
}

// ---------------- e2: logsumexp over k, accumulate NLL ----------------------
__global__ void k_e2() {
    int warp = threadIdx.x >> 5, lane = threadIdx.x & 31;
    int b = blockIdx.x * 8 + warp;
    const float* rt = &g_T[(size_t)b * K_N];
    const float* rs = &g_S2[(size_t)b * K_N];
    float vals[16];
    float mx = -1e30f;
#pragma unroll
    for (int i = 0; i < 16; i++) {
        vals[i] = rt[i * 32 + lane] + rs[i * 32 + lane];
        mx = fmaxf(mx, vals[i]);
    }
    for (int o = 16; o; o >>= 1) mx = fmaxf(mx, __shfl_xor_sync(0xffffffffu, mx, o));
    float s = 0.0f;
#pragma unroll
    for (int i = 0; i < 16; i++) s += expf(vals[i] - mx);
    for (int o = 16; o; o >>= 1) s += __shfl_xor_sync(0xffffffffu, s, o);
    if (lane == 0) {
        float logp = logf(s) + mx - 0.5f * g_r[b];
        atomicAdd(&g_acc, (double)(-logp));
    }
}

__global__ void k_init() { g_acc = 0.0; }
__global__ void k_fin(float* out) { out[0] = (float)(g_acc * (1.0 / (double)B_N)); }

// ---------------- launch ----------------
extern "C" void kernel_launch(void* const* d_in, const int* in_sizes, int n_in,
                              void* d_out, int out_size) {
    const float* x         = (const float*)d_in[0];
    const float* mu        = (const float*)d_in[1];
    const float* dir_raw   = (const float*)d_in[2];
    const float* scale_rho = (const float*)d_in[3];
    const float* psi_rho   = (const float*)d_in[4];
    const float* pi_logits = (const float*)d_in[5];
    float* out = (float*)d_out;

    cudaFuncSetAttribute(k_mma_gemm, cudaFuncAttributeMaxDynamicSharedMemorySize, SMEM_SZ);

    k_init<<<1, 1>>>();
    k_psi<<<1, 256>>>(psi_rho);
    k_cvt<<<(B_N * D_N) / (256 * 8), 256>>>(x);
    pA<<<K_N, 256>>>(dir_raw, scale_rho);
    pB<<<dim3(4, K_N), 256>>>(dir_raw, mu);
    pC<<<4, 128>>>();
    k_off<<<1, 512>>>(pi_logits);
    k_xpx<<<B_N / 8, 256>>>(x);
    dim3 gg(36, 32);
    k_mma_gemm<<<gg, 256, SMEM_SZ>>>();
    k_e2<<<B_N / 8, 256>>>();
    k_fin<<<1, 1>>>(out);
}

// round 5
// speedup vs baseline: 1.0744x; 1.0744x over previous
#include <cuda_runtime.h>
#include <cuda_bf16.h>
#include <math.h>
#include <stdint.h>

#define B_N    8192
#define K_N    512
#define D_N    2048
#define Q_N    8
#define LOG2PI 1.8378770664093453f
#define EPSC   1e-5f

// ---------------- scratch (static __device__, no allocation) ----------------
__device__ __nv_bfloat16 g_XB[(size_t)B_N * D_N];   // X in bf16
__device__ __nv_bfloat16 g_WB[(size_t)4608 * D_N];  // [512 pm | 4096 PinvW] x D, bf16
__device__ float  g_T [(size_t)B_N * K_N];          // t1[b][k], 16 MB
__device__ float  g_S2[(size_t)B_N * K_N];          // off + 0.5 v^T Minv v, 16 MB
__device__ float  g_psi_inv[D_N];
__device__ float  g_logdetPsi;
__device__ float  g_r[B_N];
__device__ float  g_alpha[K_N * 8];
__device__ float  g_Sacc[K_N * 45];
__device__ float  g_wpm[K_N * 8];
__device__ float  g_Minv[K_N * 64];                 // 0.5 * M^-1 (0.5 folded in)
__device__ float  g_logdetM[K_N];
__device__ float  g_mumu[K_N];
__device__ float  g_off[K_N];
__device__ double g_acc;

__device__ __forceinline__ float softplusf(float x) {
    return x > 20.0f ? x : log1pf(expf(x));
}
__device__ __forceinline__ uint32_t smem_u32(const void* p) {
    uint32_t a;
    asm("{ .reg .u64 t; cvta.to.shared.u64 t, %1; cvt.u32.u64 %0, t; }" : "=r"(a) : "l"(p));
    return a;
}
__device__ __forceinline__ void cp_async16(uint32_t saddr, const void* gaddr) {
    asm volatile("cp.async.cg.shared.global [%0], [%1], 16;" :: "r"(saddr), "l"(gaddr));
}

// ---------------- psi precompute ----------------
__global__ void k_psi(const float* __restrict__ psi_rho) {
    __shared__ float ssum;
    int tid = threadIdx.x;
    if (tid == 0) ssum = 0.0f;
    __syncthreads();
    float l = 0.0f;
    for (int d = tid; d < D_N; d += 256) {
        float p = softplusf(psi_rho[d]) + EPSC;
        g_psi_inv[d] = 1.0f / p;
        l += logf(p);
    }
    atomicAdd(&ssum, l);
    __syncthreads();
    if (tid == 0) g_logdetPsi = ssum;
}

// ---------------- X -> bf16 ----------------
__global__ void k_cvt(const float* __restrict__ x) {
    size_t i = ((size_t)blockIdx.x * 256 + threadIdx.x) * 8;
    float4 a = *(const float4*)(x + i);
    float4 b = *(const float4*)(x + i + 4);
    __nv_bfloat162 p0 = __float22bfloat162_rn(make_float2(a.x, a.y));
    __nv_bfloat162 p1 = __float22bfloat162_rn(make_float2(a.z, a.w));
    __nv_bfloat162 p2 = __float22bfloat162_rn(make_float2(b.x, b.y));
    __nv_bfloat162 p3 = __float22bfloat162_rn(make_float2(b.z, b.w));
    uint4 o;
    o.x = *(uint32_t*)&p0; o.y = *(uint32_t*)&p1;
    o.z = *(uint32_t*)&p2; o.w = *(uint32_t*)&p3;
    *(uint4*)(g_XB + i) = o;
}

// ---------------- pA: column norms -> alpha; zero Sacc ----------------
__global__ void pA(const float* __restrict__ dir_raw,
                   const float* __restrict__ scale_rho) {
    int k = blockIdx.x, tid = threadIdx.x;
    __shared__ float s_nsq[8];
    if (tid < 8)  s_nsq[tid] = 0.0f;
    if (tid < 45) g_Sacc[k * 45 + tid] = 0.0f;
    __syncthreads();
    const float* dirk = dir_raw + (size_t)k * D_N * Q_N;
    float ns[8];
#pragma unroll
    for (int j = 0; j < 8; j++) ns[j] = 0.0f;
    for (int d = tid; d < D_N; d += 256) {
        float4 a  = *(const float4*)(dirk + (size_t)d * 8);
        float4 b4 = *(const float4*)(dirk + (size_t)d * 8 + 4);
        ns[0] += a.x * a.x;  ns[1] += a.y * a.y;
        ns[2] += a.z * a.z;  ns[3] += a.w * a.w;
        ns[4] += b4.x * b4.x; ns[5] += b4.y * b4.y;
        ns[6] += b4.z * b4.z; ns[7] += b4.w * b4.w;
    }
#pragma unroll
    for (int j = 0; j < 8; j++) atomicAdd(&s_nsq[j], ns[j]);
    __syncthreads();
    if (tid < 8) {
        float sp = softplusf(scale_rho[k * 8 + tid]);
        g_alpha[k * 8 + tid] = sp / fmaxf(sqrtf(s_nsq[tid]), EPSC);
    }
}

// ---------------- pB: S/wm/mumu partials + Wcat writes (4-way D split) ------
__global__ void pB(const float* __restrict__ dir_raw,
                   const float* __restrict__ mu) {
    int k = blockIdx.y, chunk = blockIdx.x, tid = threadIdx.x;
    __shared__ float s_acc[45];
    if (tid < 45) s_acc[tid] = 0.0f;
    __syncthreads();

    const float* dirk = dir_raw + (size_t)k * D_N * Q_N;
    const float* muk  = mu + (size_t)k * D_N;
    float al[8];
#pragma unroll
    for (int j = 0; j < 8; j++) al[j] = g_alpha[k * 8 + j];

    float S[36], wm[8], mm = 0.0f;
#pragma unroll
    for (int i = 0; i < 36; i++) S[i] = 0.0f;
#pragma unroll
    for (int i = 0; i < 8; i++) wm[i] = 0.0f;

    int d0 = chunk * 512;
#pragma unroll
    for (int it = 0; it < 2; it++) {
        int d = d0 + tid + it * 256;
        float dv[8];
        float4 a  = *(const float4*)(dirk + (size_t)d * 8);
        float4 b4 = *(const float4*)(dirk + (size_t)d * 8 + 4);
        dv[0] = a.x; dv[1] = a.y; dv[2] = a.z; dv[3] = a.w;
        dv[4] = b4.x; dv[5] = b4.y; dv[6] = b4.z; dv[7] = b4.w;
        float pi = g_psi_inv[d];
        float m  = muk[d];
        float pim = pi * m;
        mm += m * pim;
        int idx = 0;
#pragma unroll
        for (int i = 0; i < 8; i++) {
            float pdi = pi * dv[i];
            wm[i] += m * pdi;
#pragma unroll
            for (int j = 0; j <= i; j++) S[idx++] += pdi * dv[j];
        }
        g_WB[(size_t)k * D_N + d] = __float2bfloat16(pim);
#pragma unroll
        for (int j = 0; j < 8; j++)
            g_WB[(size_t)(K_N + k * 8 + j) * D_N + d] = __float2bfloat16(pi * al[j] * dv[j]);
    }
#pragma unroll
    for (int i = 0; i < 36; i++) atomicAdd(&s_acc[i], S[i]);
#pragma unroll
    for (int j = 0; j < 8; j++) atomicAdd(&s_acc[36 + j], wm[j]);
    atomicAdd(&s_acc[44], mm);
    __syncthreads();
    if (tid < 45) atomicAdd(&g_Sacc[k * 45 + tid], s_acc[tid]);
}

// ---------------- pC: per-k Cholesky / inverse (one thread per k) -----------
__global__ void pC() {
    int k = blockIdx.x * 128 + threadIdx.x;
    if (k >= K_N) return;
    float al[8], acc45[45];
#pragma unroll
    for (int j = 0; j < 8; j++) al[j] = g_alpha[k * 8 + j];
    for (int i = 0; i < 45; i++) acc45[i] = g_Sacc[k * 45 + i];

    float Mm[8][8];
    int idx = 0;
    for (int i = 0; i < 8; i++)
        for (int j = 0; j <= i; j++)
            Mm[i][j] = al[i] * al[j] * acc45[idx++] + (i == j ? 1.0f : 0.0f);
    for (int i = 0; i < 8; i++) {
        for (int j = 0; j <= i; j++) {
            float s = Mm[i][j];
            for (int p = 0; p < j; p++) s -= Mm[i][p] * Mm[j][p];
            if (i == j) Mm[i][i] = sqrtf(s);
            else        Mm[i][j] = s / Mm[j][j];
        }
    }
    float ld = 0.0f;
    for (int i = 0; i < 8; i++) ld += logf(Mm[i][i]);
    g_logdetM[k] = 2.0f * ld;
    g_mumu[k]    = acc45[44];
    for (int j = 0; j < 8; j++) g_wpm[k * 8 + j] = al[j] * acc45[36 + j];

    float Li[8][8];
    for (int i = 0; i < 8; i++)
        for (int j = 0; j < 8; j++) Li[i][j] = 0.0f;
    for (int c = 0; c < 8; c++) {
        for (int i = c; i < 8; i++) {
            float s = (i == c) ? 1.0f : 0.0f;
            for (int p = c; p < i; p++) s -= Mm[i][p] * Li[p][c];
            Li[i][c] = s / Mm[i][i];
        }
    }
    for (int i = 0; i < 8; i++)
        for (int j = 0; j < 8; j++) {
            float s = 0.0f;
            for (int m2 = 0; m2 < 8; m2++) s += Li[m2][i] * Li[m2][j];
            g_Minv[(size_t)k * 64 + i * 8 + j] = 0.5f * s;
        }
}

// ---------------- per-k offset ----------------
__global__ void k_off(const float* __restrict__ pi_logits) {
    __shared__ float buf[512];
    int t = threadIdx.x;
    float v = pi_logits[t];
    buf[t] = v;
    __syncthreads();
    for (int s = 256; s > 0; s >>= 1) {
        if (t < s) buf[t] = fmaxf(buf[t], buf[t + s]);
        __syncthreads();
    }
    float mx = buf[0];
    __syncthreads();
    buf[t] = expf(v - mx);
    __syncthreads();
    for (int s = 256; s > 0; s >>= 1) {
        if (t < s) buf[t] += buf[t + s];
        __syncthreads();
    }
    float lse = logf(buf[0]) + mx;
    g_off[t] = -0.5f * ((float)D_N * LOG2PI + g_logdetPsi + g_logdetM[t] + g_mumu[t])
               + v - lse;
}

// ---------------- r[b] = x^T Psi^-1 x ----------------
__global__ void k_xpx(const float* __restrict__ x) {
    int warp = threadIdx.x >> 5, lane = threadIdx.x & 31;
    int b = blockIdx.x * 8 + warp;
    const float* xb = x + (size_t)b * D_N;
    float s = 0.0f;
    for (int d = lane * 4; d < D_N; d += 128) {
        float4 xv = *(const float4*)(xb + d);
        float4 pv = *(const float4*)(g_psi_inv + d);
        s += xv.x * xv.x * pv.x + xv.y * xv.y * pv.y
           + xv.z * xv.z * pv.z + xv.w * xv.w * pv.w;
    }
    for (int o = 16; o; o >>= 1) s += __shfl_xor_sync(0xffffffffu, s, o);
    if (lane == 0) g_r[b] = s;
}

// ---------------- bf16 MMA GEMM + fused quad epilogue -----------------------
// CTA 128x128, warp tile 64x32, BK=32, 3-stage cp.async, occupancy 2.
#define BK       32
#define KBLOCKS  (D_N / BK)      // 64
#define STAGES   3
#define TILE_A   8192            // 128 rows * 64B
#define TILE_B   8192
#define TILE_AB  (TILE_A + TILE_B)

__global__ void __launch_bounds__(256, 2) k_mma_gemm() {
    __shared__ __align__(128) char smem[STAGES * TILE_AB];
    const int tid  = threadIdx.x;
    const int wid  = tid >> 5;
    const int lane = tid & 31;
    const int warp_m = wid & 1;    // 2 x 64 rows
    const int warp_n = wid >> 1;   // 4 x 32 cols
    const int bx = blockIdx.x;     // 0..35 (bx<4 -> t1 region, else quad region)
    const int by = blockIdx.y;     // 0..63

    const uint32_t sbase = smem_u32(smem);
    const __nv_bfloat16* Ag = g_XB + (size_t)(by * 128) * D_N;
    const __nv_bfloat16* Bg = g_WB + (size_t)(bx * 128) * D_N;

    auto load_stage = [&](int s, int kb) {
        uint32_t aB = sbase + s * TILE_AB;
        uint32_t bB = aB + TILE_A;
#pragma unroll
        for (int i = 0; i < 2; i++) {
            int id  = tid + i * 256;
            int row = id >> 2;
            int ch  = id & 3;
            int sw  = ch ^ ((row >> 1) & 3);
            cp_async16(aB + row * 64 + sw * 16, Ag + (size_t)row * D_N + kb * BK + ch * 8);
            cp_async16(bB + row * 64 + sw * 16, Bg + (size_t)row * D_N + kb * BK + ch * 8);
        }
        asm volatile("cp.async.commit_group;");
    };

    float acc[4][4][4];
#pragma unroll
    for (int mi = 0; mi < 4; mi++)
#pragma unroll
        for (int ni = 0; ni < 4; ni++)
#pragma unroll
            for (int j = 0; j < 4; j++) acc[mi][ni][j] = 0.0f;

    load_stage(0, 0);
    load_stage(1, 1);

    for (int kb = 0; kb < KBLOCKS; kb++) {
        if (kb + 2 < KBLOCKS) load_stage((kb + 2) % STAGES, kb + 2);
        if (kb + 2 < KBLOCKS)       asm volatile("cp.async.wait_group 2;");
        else if (kb + 2 == KBLOCKS) asm volatile("cp.async.wait_group 1;");
        else                        asm volatile("cp.async.wait_group 0;");
        __syncthreads();
        uint32_t aB = sbase + (kb % STAGES) * TILE_AB;
        uint32_t bB = aB + TILE_A;
#pragma unroll
        for (int ks = 0; ks < 2; ks++) {
            uint32_t a[4][4], b[4][2];
#pragma unroll
            for (int mi = 0; mi < 4; mi++) {
                int r  = warp_m * 64 + mi * 16 + (lane & 15);
                int ch = ks * 2 + (lane >> 4);
                uint32_t ad = aB + r * 64 + ((ch ^ ((r >> 1) & 3)) << 4);
                asm volatile("ldmatrix.sync.aligned.m8n8.x4.shared.b16 {%0,%1,%2,%3}, [%4];"
                             : "=r"(a[mi][0]), "=r"(a[mi][1]), "=r"(a[mi][2]), "=r"(a[mi][3])
                             : "r"(ad));
            }
            int c = lane & 15;
#pragma unroll
            for (int ni = 0; ni < 4; ni++) {
                int r  = warp_n * 32 + ni * 8 + (c & 7);
                int ch = ks * 2 + (c >> 3);
                uint32_t bd = bB + r * 64 + ((ch ^ ((r >> 1) & 3)) << 4);
                asm volatile("ldmatrix.sync.aligned.m8n8.x2.shared.b16 {%0,%1}, [%2];"
                             : "=r"(b[ni][0]), "=r"(b[ni][1]) : "r"(bd));
            }
#pragma unroll
            for (int mi = 0; mi < 4; mi++)
#pragma unroll
                for (int ni = 0; ni < 4; ni++) {
                    asm volatile(
                        "mma.sync.aligned.m16n8k16.row.col.f32.bf16.bf16.f32 "
                        "{%0,%1,%2,%3}, {%4,%5,%6,%7}, {%8,%9}, {%0,%1,%2,%3};"
                        : "+f"(acc[mi][ni][0]), "+f"(acc[mi][ni][1]),
                          "+f"(acc[mi][ni][2]), "+f"(acc[mi][ni][3])
                        : "r"(a[mi][0]), "r"(a[mi][1]), "r"(a[mi][2]), "r"(a[mi][3]),
                          "r"(b[ni][0]), "r"(b[ni][1]));
                }
        }
        __syncthreads();
    }

    const int gq = lane >> 2;   // 0..7
    const int tg = lane & 3;    // 0..3

    if (bx < 4) {
        // t1 region: plain write to g_T
#pragma unroll
        for (int mi = 0; mi < 4; mi++) {
            int r0 = by * 128 + warp_m * 64 + mi * 16 + gq;
            int r1 = r0 + 8;
#pragma unroll
            for (int ni = 0; ni < 4; ni++) {
                int col = bx * 128 + warp_n * 32 + ni * 8 + tg * 2;
                *(float2*)&g_T[(size_t)r0 * K_N + col] = make_float2(acc[mi][ni][0], acc[mi][ni][1]);
                *(float2*)&g_T[(size_t)r1 * K_N + col] = make_float2(acc[mi][ni][2], acc[mi][ni][3]);
            }
        }
        return;
    }

    // quad region: fused v^T (0.5 Minv) v epilogue (smem reused from tiles)
    float* sM = (float*)smem;            // 16 k x 64
    float* sW = sM + 16 * 64;            // 16 k x 8
    float* sO = sW + 16 * 8;             // 16
    int k0 = (bx - 4) * 16;
    for (int t = tid; t < 1024; t += 256)
        sM[t] = g_Minv[(size_t)(k0 + (t >> 6)) * 64 + (t & 63)];
    if (tid < 128) sW[tid] = g_wpm[k0 * 8 + tid];
    if (tid < 16)  sO[tid] = g_off[k0 + tid];
    __syncthreads();

    const unsigned FULL = 0xffffffffu;
    const bool oddg = (tg & 1);
    const bool hig  = (tg & 2);
#pragma unroll
    for (int ni = 0; ni < 4; ni++) {
        int k_loc = warp_n * 4 + ni;
        float m0[8], m1[8];
#pragma unroll
        for (int j = 0; j < 8; j++) {
            m0[j] = sM[k_loc * 64 + (2 * tg) * 8 + j];
            m1[j] = sM[k_loc * 64 + (2 * tg + 1) * 8 + j];
        }
        float w0 = sW[k_loc * 8 + 2 * tg];
        float w1 = sW[k_loc * 8 + 2 * tg + 1];
        float offk = sO[k_loc];
        int kg = k0 + k_loc;
#pragma unroll
        for (int mi = 0; mi < 4; mi++) {
            int r0 = by * 128 + warp_m * 64 + mi * 16 + gq;
            float q[2];
#pragma unroll
            for (int half = 0; half < 2; half++) {
                float va = acc[mi][ni][half * 2 + 0] - w0;   // j = 2tg
                float vb = acc[mi][ni][half * 2 + 1] - w1;   // j = 2tg+1
                float pa = __shfl_xor_sync(FULL, va, 1);
                float pb = __shfl_xor_sync(FULL, vb, 1);
                float u0 = oddg ? pa : va, u1 = oddg ? pb : vb;
                float u2 = oddg ? va : pa, u3 = oddg ? vb : pb;
                float x0 = __shfl_xor_sync(FULL, u0, 2);
                float x1 = __shfl_xor_sync(FULL, u1, 2);
                float x2 = __shfl_xor_sync(FULL, u2, 2);
                float x3 = __shfl_xor_sync(FULL, u3, 2);
                float v0 = hig ? x0 : u0, v1 = hig ? x1 : u1;
                float v2 = hig ? x2 : u2, v3 = hig ? x3 : u3;
                float v4 = hig ? u0 : x0, v5 = hig ? u1 : x1;
                float v6 = hig ? u2 : x2, v7 = hig ? u3 : x3;
                float s0 = m0[0]*v0 + m0[1]*v1 + m0[2]*v2 + m0[3]*v3
                         + m0[4]*v4 + m0[5]*v5 + m0[6]*v6 + m0[7]*v7;
                float s1 = m1[0]*v0 + m1[1]*v1 + m1[2]*v2 + m1[3]*v3
                         + m1[4]*v4 + m1[5]*v5 + m1[6]*v6 + m1[7]*v7;
                float qp = va * s0 + vb * s1;
                qp += __shfl_xor_sync(FULL, qp, 1);
                qp += __shfl_xor_sync(FULL, qp, 2);
                q[half] = qp;
            }
            if (tg == 0) g_S2[(size_t)r0 * K_N + kg]       = offk + q[0];
            if (tg == 1) g_S2[(size_t)(r0 + 8) * K_N + kg] = offk + q[1];
        }
    }
}

// ---------------- e2: logsumexp over k, accumulate NLL ----------------------
__global__ void k_e2() {
    int warp = threadIdx.x >> 5, lane = threadIdx.x & 31;
    int b = blockIdx.x * 8 + warp;
    const float* rt = &g_T[(size_t)b * K_N];
    const float* rs = &g_S2[(size_t)b * K_N];
    float vals[16];
    float mx = -1e30f;
#pragma unroll
    for (int i = 0; i < 16; i++) {
        vals[i] = rt[i * 32 + lane] + rs[i * 32 + lane];
        mx = fmaxf(mx, vals[i]);
    }
    for (int o = 16; o; o >>= 1) mx = fmaxf(mx, __shfl_xor_sync(0xffffffffu, mx, o));
    float s = 0.0f;
#pragma unroll
    for (int i = 0; i < 16; i++) s += expf(vals[i] - mx);
    for (int o = 16; o; o >>= 1) s += __shfl_xor_sync(0xffffffffu, s, o);
    if (lane == 0) {
        float logp = logf(s) + mx - 0.5f * g_r[b];
        atomicAdd(&g_acc, (double)(-logp));
    }
}

__global__ void k_init() { g_acc = 0.0; }
__global__ void k_fin(float* out) { out[0] = (float)(g_acc * (1.0 / (double)B_N)); }

// ---------------- launch ----------------
extern "C" void kernel_launch(void* const* d_in, const int* in_sizes, int n_in,
                              void* d_out, int out_size) {
    const float* x         = (const float*)d_in[0];
    const float* mu        = (const float*)d_in[1];
    const float* dir_raw   = (const float*)d_in[2];
    const float* scale_rho = (const float*)d_in[3];
    const float* psi_rho   = (const float*)d_in[4];
    const float* pi_logits = (const float*)d_in[5];
    float* out = (float*)d_out;

    k_init<<<1, 1>>>();
    k_psi<<<1, 256>>>(psi_rho);
    k_cvt<<<(B_N * D_N) / (256 * 8), 256>>>(x);
    pA<<<K_N, 256>>>(dir_raw, scale_rho);
    pB<<<dim3(4, K_N), 256>>>(dir_raw, mu);
    pC<<<4, 128>>>();
    k_off<<<1, 512>>>(pi_logits);
    k_xpx<<<B_N / 8, 256>>>(x);
    dim3 gg(36, 64);
    k_mma_gemm<<<gg, 256>>>();
    k_e2<<<B_N / 8, 256>>>();
    k_fin<<<1, 1>>>(out);
}